// round 12
// baseline (speedup 1.0000x reference)
#include <cuda_runtime.h>
#include <cstdint>

// Fixed problem: n=4, c=16, h=w=64, patch=3
#define NB 4
#define CH 16
#define W 64
#define HW 4096
#define NDIAG 127
#define RST 67            // Rbuf row stride (67 % 32 = 3 -> conflict-free cols)
#define ABST 68           // A/B buffer row stride
#define NSTG 1122         // 17 rows x 66 staged values per operand

#define CY(v) (min(max((v), 0), 63))

__device__ float g_sm2[NB * CH * HW];   // -2 * s
__device__ float g_eS[NB * HW];
__device__ float g_eT[NB * HW];
__device__ unsigned long long g_best[NB * HW];

#define CPA4(dst, src) \
    asm volatile("cp.async.ca.shared.global [%0], [%1], 4;\n" ::"r"(dst), "l"(src))

// ---------------------------------------------------------------------------
// Per-pixel channel sum of squares (eS / eT); y==0 also writes -2*s and
// resets g_best.
// ---------------------------------------------------------------------------
__global__ void norm1_kernel(const float* __restrict__ s, const float* __restrict__ t) {
    int idx = blockIdx.x * blockDim.x + threadIdx.x;
    if (idx >= NB * HW) return;
    const float* src = blockIdx.y ? t : s;
    int b = idx >> 12, pix = idx & (HW - 1);
    float acc = 0.f;
#pragma unroll
    for (int c = 0; c < CH; c++) {
        float v = src[((size_t)(b * CH + c) << 12) + pix];
        if (!blockIdx.y) g_sm2[((size_t)(b * CH + c) << 12) + pix] = -2.f * v;
        acc = fmaf(v, v, acc);
    }
    if (blockIdx.y) {
        g_eT[idx] = acc;
    } else {
        g_eS[idx] = acc;
        g_best[idx] = ~0ull;
    }
}

// ---------------------------------------------------------------------------
// Diagonal sweep kernel. Block = (batch b, diagonal d = jy - iy), 508 blocks.
// R~(p, p+d)(ix~, jx~) is a K=18 GEMM folding both norms:
//   ch 0..15: (-2 s)[c][CY(p-1)][CY(ix~-1)] * t[c][CY(p+d-1)][CY(jx~-1)]
//   ch 16   : eS~(p, ix~) * 1
//   ch 17   : 1 * eT~(p+d, jx~)
// d2(iy, jy=iy+d)(ix,jx) = sum_uy Gx(p=iy+uy), Gx = diag-x-stencil of R~.
// Double-buffered cp.async staging (register-free); argmin merges to global
// via atomicMin on packed key (d2bits<<12 | j) = exact first occurrence.
// ---------------------------------------------------------------------------
__global__ __launch_bounds__(256, 3) void nn_kernel(const float* __restrict__ t) {
    __shared__ float Abuf[2][18 * ABST];
    __shared__ float Bbuf[2][18 * ABST];
    __shared__ float Rbuf[66 * RST];

    const int tid = threadIdx.x;
    const int blk = blockIdx.x;
    const int kk = blk >> 2;            // diagonal index 0..126 (|d| ascending)
    const int b = blk & 3;
    const int d = (kk == 0) ? 0 : ((kk & 1) ? ((kk + 1) >> 1) : -(kk >> 1));
    const int lo = max(0, -d);
    const int steps = 66 - abs(d);

    const float* tB = t + ((size_t)b * CH << 12);
    const float* s2B = g_sm2 + ((size_t)b * CH << 12);
    const float* eSb = g_eS + b * HW;
    const float* eTb = g_eT + b * HW;

    const unsigned aS0 = (unsigned)__cvta_generic_to_shared(&Abuf[0][0]);
    const unsigned aS1 = (unsigned)__cvta_generic_to_shared(&Abuf[1][0]);
    const unsigned bS0 = (unsigned)__cvta_generic_to_shared(&Bbuf[0][0]);
    const unsigned bS1 = (unsigned)__cvta_generic_to_shared(&Bbuf[1][0]);

    // ---- staging precompute: 5 (A,B) elements per thread ----
    const float* pA[5]; const float* pB[5];
    unsigned dA[5], dB[5]; bool val[5];
#pragma unroll
    for (int q = 0; q < 5; q++) {
        int u = tid + 256 * q;
        val[q] = (u < NSTG);
        int uu = val[q] ? u : 0;
        int m = uu / 66, xx = uu - 66 * m;
        int gx = CY(xx - 1);
        pA[q] = (m < 16) ? (s2B + (m << 12) + gx) : (eSb + gx);
        dA[q] = (m * ABST + xx) * 4;
        pB[q] = (m < 16) ? (tB + (m << 12) + gx) : (eTb + gx);
        dB[q] = (((m == 16) ? 17 : m) * ABST + xx) * 4;
    }
    // constant channels in both buffers: A ch17 = 1, B ch16 = 1
    if (tid < 66) {
        Abuf[0][17 * ABST + tid] = 1.f;
        Abuf[1][17 * ABST + tid] = 1.f;
        Bbuf[0][16 * ABST + tid] = 1.f;
        Bbuf[1][16 * ABST + tid] = 1.f;
    }

    // prologue: async-stage p = lo into buf0
    {
        int ra = CY(lo - 1) * W, rb = CY(lo + d - 1) * W;
#pragma unroll
        for (int q = 0; q < 5; q++) if (val[q]) {
            CPA4(aS0 + dA[q], pA[q] + ra);
            CPA4(bS0 + dB[q], pB[q] + rb);
        }
        asm volatile("cp.async.commit_group;\n");
    }

    // GEMM fragment mapping: 242 active threads, 3 ix~ x 6 jx~ each
    const bool act = tid < 242;
    const int ti = act ? (tid / 11) : 0;
    const int tj = act ? (tid - 11 * ti) : 0;

    // epilogue mapping: query ix = eix, jx band = 16*eg
    const int eix = tid & 63;
    const int eg = tid >> 6;
    const int ejx0 = eg << 4;
    const float* R0 = Rbuf + eix * RST + ejx0;
    const float* R1 = Rbuf + (eix + 1) * RST + ejx0 + 1;
    const float* R2 = Rbuf + (eix + 2) * RST + ejx0 + 2;
    unsigned long long* gb = g_best + b * HW + eix;

    float A1[16], A2[16];
#pragma unroll
    for (int jj = 0; jj < 16; jj++) { A1[jj] = 0.f; A2[jj] = 0.f; }

    for (int ss = 0; ss < steps; ss++) {
        const int cur = ss & 1;
        asm volatile("cp.async.wait_group 0;\n" ::: "memory");
        __syncthreads();   // buf[cur] staged; prev epilogue done with Rbuf

        // ---- K=18 GEMM from buf[cur] -> R~ tile ----
        if (act) {
            float acc[3][6];
#pragma unroll
            for (int m = 0; m < 3; m++)
#pragma unroll
                for (int n = 0; n < 6; n++) acc[m][n] = 0.f;
            const float* Ap = Abuf[cur] + 3 * ti;
            const float* Bp = Bbuf[cur] + 6 * tj;
#pragma unroll 6
            for (int k = 0; k < 18; k++) {
                float a0 = Ap[k * ABST], a1 = Ap[k * ABST + 1], a2 = Ap[k * ABST + 2];
                float2 b0 = *(const float2*)(Bp + k * ABST);
                float2 b1 = *(const float2*)(Bp + k * ABST + 2);
                float2 b2 = *(const float2*)(Bp + k * ABST + 4);
                acc[0][0] = fmaf(a0, b0.x, acc[0][0]);
                acc[0][1] = fmaf(a0, b0.y, acc[0][1]);
                acc[0][2] = fmaf(a0, b1.x, acc[0][2]);
                acc[0][3] = fmaf(a0, b1.y, acc[0][3]);
                acc[0][4] = fmaf(a0, b2.x, acc[0][4]);
                acc[0][5] = fmaf(a0, b2.y, acc[0][5]);
                acc[1][0] = fmaf(a1, b0.x, acc[1][0]);
                acc[1][1] = fmaf(a1, b0.y, acc[1][1]);
                acc[1][2] = fmaf(a1, b1.x, acc[1][2]);
                acc[1][3] = fmaf(a1, b1.y, acc[1][3]);
                acc[1][4] = fmaf(a1, b2.x, acc[1][4]);
                acc[1][5] = fmaf(a1, b2.y, acc[1][5]);
                acc[2][0] = fmaf(a2, b0.x, acc[2][0]);
                acc[2][1] = fmaf(a2, b0.y, acc[2][1]);
                acc[2][2] = fmaf(a2, b1.x, acc[2][2]);
                acc[2][3] = fmaf(a2, b1.y, acc[2][3]);
                acc[2][4] = fmaf(a2, b2.x, acc[2][4]);
                acc[2][5] = fmaf(a2, b2.y, acc[2][5]);
            }
#pragma unroll
            for (int m = 0; m < 3; m++)
#pragma unroll
                for (int n = 0; n < 6; n++)
                    Rbuf[(3 * ti + m) * RST + 6 * tj + n] = acc[m][n];
        }

        // ---- async-stage next row pair into buf[cur^1] ----
        if (ss + 1 < steps) {
            int pn = lo + ss + 1;
            int ra = CY(pn - 1) * W, rb = CY(pn + d - 1) * W;
            unsigned aS = cur ? aS0 : aS1;
            unsigned bS = cur ? bS0 : bS1;
#pragma unroll
            for (int q = 0; q < 5; q++) if (val[q]) {
                CPA4(aS + dA[q], pA[q] + ra);
                CPA4(bS + dB[q], pB[q] + rb);
            }
        }
        asm volatile("cp.async.commit_group;\n");
        __syncthreads();   // Rbuf writes visible

        // ---- epilogue: diag-x-stencil, sliding window, argmin on finish ----
        const bool fin = (ss >= 2);
        const int jy = lo + ss - 2 + d;
        unsigned long long cand = ~0ull;
        const unsigned jrow = (unsigned)(jy * W + ejx0);
#pragma unroll
        for (int jj = 0; jj < 16; jj++) {
            float g = R0[jj] + R1[jj] + R2[jj];
            if (fin) {
                float d2 = A2[jj] + g;
                unsigned long long key =
                    ((unsigned long long)__float_as_uint(d2) << 12) | (jrow + jj);
                cand = key < cand ? key : cand;
            }
            A2[jj] = A1[jj] + g;
            A1[jj] = g;
        }
        if (fin) {
            int iy = lo + ss - 2;
            atomicMin(gb + iy * W, cand);
        }
    }
}

// ---------------------------------------------------------------------------
// Decode packed keys -> (jy, jx, d2).
// ---------------------------------------------------------------------------
__global__ void reduce_kernel(float* __restrict__ out) {
    int idx = blockIdx.x * blockDim.x + threadIdx.x;
    if (idx >= NB * HW) return;
    int b = idx >> 12, q = idx & (HW - 1);
    unsigned long long best = g_best[idx];
    int j = (int)(best & 4095u);
    float d2 = __uint_as_float((unsigned)(best >> 12));
    out[(size_t)b * 2 * HW + q]                    = (float)(j >> 6);
    out[(size_t)b * 2 * HW + HW + q]               = (float)(j & 63);
    out[(size_t)NB * 2 * HW + (size_t)b * HW + q]  = d2;
}

extern "C" void kernel_launch(void* const* d_in, const int* in_sizes, int n_in,
                              void* d_out, int out_size) {
    const float* s = (const float*)d_in[0];
    const float* t = (const float*)d_in[1];
    float* out = (float*)d_out;

    norm1_kernel<<<dim3((NB * HW + 255) / 256, 2), 256>>>(s, t);
    nn_kernel<<<NDIAG * NB, 256>>>(t);
    reduce_kernel<<<(NB * HW + 255) / 256, 256>>>(out);
}

// round 13
// speedup vs baseline: 1.1919x; 1.1919x over previous
#include <cuda_runtime.h>
#include <cstdint>

// Fixed problem: n=4, c=16, h=w=64, patch=3
#define NB 4
#define CH 16
#define W 64
#define HW 4096
#define NDIAG 127
#define RST 67            // Rbuf row stride (67 % 32 = 3 -> conflict-free cols)
#define ABST 68           // A/B buffer row stride
#define NSTG 1122         // 17 rows x 66 staged values per operand
#define ABSZ (18 * ABST)
#define SMEM_BYTES ((8 * ABSZ + 2 * 66 * RST) * 4)   // 74544

#define CY(v) (min(max((v), 0), 63))

__device__ float g_sm2[NB * CH * HW];   // -2 * s
__device__ float g_eS[NB * HW];
__device__ float g_eT[NB * HW];
__device__ unsigned long long g_best[NB * HW];

// ---------------------------------------------------------------------------
// Per-pixel channel sum of squares (eS / eT); y==0 also writes -2*s and
// resets g_best.
// ---------------------------------------------------------------------------
__global__ void norm1_kernel(const float* __restrict__ s, const float* __restrict__ t) {
    int idx = blockIdx.x * blockDim.x + threadIdx.x;
    if (idx >= NB * HW) return;
    const float* src = blockIdx.y ? t : s;
    int b = idx >> 12, pix = idx & (HW - 1);
    float acc = 0.f;
#pragma unroll
    for (int c = 0; c < CH; c++) {
        float v = src[((size_t)(b * CH + c) << 12) + pix];
        if (!blockIdx.y) g_sm2[((size_t)(b * CH + c) << 12) + pix] = -2.f * v;
        acc = fmaf(v, v, acc);
    }
    if (blockIdx.y) {
        g_eT[idx] = acc;
    } else {
        g_eS[idx] = acc;
        g_best[idx] = ~0ull;
    }
}

// ---------------------------------------------------------------------------
// Diagonal sweep, merged-pair steps. Block = (batch b, diagonal d = jy - iy).
// Per iteration: TWO row-pairs p=lo+2it, p+1 -> two K=18 GEMM tiles
// (norm-folded channels: 16x (-2s)*t, eS*1, 1*eT) -> Rbuf0/Rbuf1, then
// epilogue finishes two iy rows via the sliding window
//   d2(iy)   = A2 + g0
//   d2(iy+1) = A1 + g0 + g1,  A2' = g0+g1, A1' = g1
// Argmin merged to global atomicMin on packed key (d2bits<<12 | j).
// ---------------------------------------------------------------------------
__global__ __launch_bounds__(256, 2) void nn_kernel(const float* __restrict__ t) {
    extern __shared__ float sm[];
    float* Ab = sm;                       // 4 sets of [18][ABST]
    float* Bb = sm + 4 * ABSZ;            // 4 sets of [18][ABST]
    float* Rbuf0 = sm + 8 * ABSZ;         // [66][RST]
    float* Rbuf1 = Rbuf0 + 66 * RST;      // [66][RST]

    const int tid = threadIdx.x;
    const int blk = blockIdx.x;
    const int kk = blk >> 2;              // diagonal index 0..126
    const int b = blk & 3;
    const int d = (kk == 0) ? 0 : ((kk & 1) ? ((kk + 1) >> 1) : -(kk >> 1));
    const int lo = max(0, -d);
    const int steps = 66 - abs(d);
    const int nIt = (steps + 1) >> 1;

    const float* tB = t + ((size_t)b * CH << 12);
    const float* s2B = g_sm2 + ((size_t)b * CH << 12);
    const float* eSb = g_eS + b * HW;
    const float* eTb = g_eT + b * HW;

    // ---- staging precompute: 5 (A,B) elements per thread ----
    const float* pA[5]; const float* pB[5];
    unsigned dA[5], dB[5]; bool val[5];
#pragma unroll
    for (int q = 0; q < 5; q++) {
        int u = tid + 256 * q;
        val[q] = (u < NSTG);
        int uu = val[q] ? u : 0;
        int m = uu / 66, xx = uu - 66 * m;
        int gx = CY(xx - 1);
        pA[q] = (m < 16) ? (s2B + (m << 12) + gx) : (eSb + gx);
        dA[q] = m * ABST + xx;
        pB[q] = (m < 16) ? (tB + (m << 12) + gx) : (eTb + gx);
        dB[q] = ((m == 16) ? 17 : m) * ABST + xx;
    }
    // constant channels in all 4 sets: A ch17 = 1, B ch16 = 1
    if (tid < 66) {
#pragma unroll
        for (int s4 = 0; s4 < 4; s4++) {
            Ab[s4 * ABSZ + 17 * ABST + tid] = 1.f;
            Bb[s4 * ABSZ + 16 * ABST + tid] = 1.f;
        }
    }

    auto ldpair = [&](int p, float* ra, float* rb) {
        int raw = CY(p - 1) * W, rbw = CY(p + d - 1) * W;
#pragma unroll
        for (int q = 0; q < 5; q++) if (val[q]) {
            ra[q] = __ldg(pA[q] + raw);
            rb[q] = __ldg(pB[q] + rbw);
        }
    };
    auto stpair = [&](int set, const float* ra, const float* rb) {
#pragma unroll
        for (int q = 0; q < 5; q++) if (val[q]) {
            Ab[set * ABSZ + dA[q]] = ra[q];
            Bb[set * ABSZ + dB[q]] = rb[q];
        }
    };

    // GEMM fragment mapping: 242 active threads, 3 ix~ x 6 jx~ each
    const bool act = tid < 242;
    const int ti = act ? (tid / 11) : 0;
    const int tj = act ? (tid - 11 * ti) : 0;

    auto gemm = [&](int set, float* Rb) {
        if (act) {
            float acc[3][6];
#pragma unroll
            for (int m = 0; m < 3; m++)
#pragma unroll
                for (int n = 0; n < 6; n++) acc[m][n] = 0.f;
            const float* Ap = Ab + set * ABSZ + 3 * ti;
            const float* Bp = Bb + set * ABSZ + 6 * tj;
#pragma unroll 6
            for (int k = 0; k < 18; k++) {
                float a0 = Ap[k * ABST], a1 = Ap[k * ABST + 1], a2 = Ap[k * ABST + 2];
                float2 b0 = *(const float2*)(Bp + k * ABST);
                float2 b1 = *(const float2*)(Bp + k * ABST + 2);
                float2 b2 = *(const float2*)(Bp + k * ABST + 4);
                acc[0][0] = fmaf(a0, b0.x, acc[0][0]);
                acc[0][1] = fmaf(a0, b0.y, acc[0][1]);
                acc[0][2] = fmaf(a0, b1.x, acc[0][2]);
                acc[0][3] = fmaf(a0, b1.y, acc[0][3]);
                acc[0][4] = fmaf(a0, b2.x, acc[0][4]);
                acc[0][5] = fmaf(a0, b2.y, acc[0][5]);
                acc[1][0] = fmaf(a1, b0.x, acc[1][0]);
                acc[1][1] = fmaf(a1, b0.y, acc[1][1]);
                acc[1][2] = fmaf(a1, b1.x, acc[1][2]);
                acc[1][3] = fmaf(a1, b1.y, acc[1][3]);
                acc[1][4] = fmaf(a1, b2.x, acc[1][4]);
                acc[1][5] = fmaf(a1, b2.y, acc[1][5]);
                acc[2][0] = fmaf(a2, b0.x, acc[2][0]);
                acc[2][1] = fmaf(a2, b0.y, acc[2][1]);
                acc[2][2] = fmaf(a2, b1.x, acc[2][2]);
                acc[2][3] = fmaf(a2, b1.y, acc[2][3]);
                acc[2][4] = fmaf(a2, b2.x, acc[2][4]);
                acc[2][5] = fmaf(a2, b2.y, acc[2][5]);
            }
#pragma unroll
            for (int m = 0; m < 3; m++)
#pragma unroll
                for (int n = 0; n < 6; n++)
                    Rb[(3 * ti + m) * RST + 6 * tj + n] = acc[m][n];
        }
    };

    // prologue: stage ss = 0,1 into sets 0,1
    {
        float ra[5], rb[5];
        ldpair(lo, ra, rb);     stpair(0, ra, rb);
        ldpair(lo + 1, ra, rb); stpair(1, ra, rb);
    }

    // epilogue mapping: query ix = eix, jx band = 16*eg
    const int eix = tid & 63;
    const int eg = tid >> 6;
    const int ejx0 = eg << 4;
    const int ro = eix * RST + ejx0;
    const float* R00 = Rbuf0 + ro;
    const float* R01 = Rbuf0 + ro + RST + 1;
    const float* R02 = Rbuf0 + ro + 2 * RST + 2;
    const float* R10 = Rbuf1 + ro;
    const float* R11 = Rbuf1 + ro + RST + 1;
    const float* R12 = Rbuf1 + ro + 2 * RST + 2;
    unsigned long long* gb = g_best + b * HW + eix;

    float A1[16], A2[16];
#pragma unroll
    for (int jj = 0; jj < 16; jj++) { A1[jj] = 0.f; A2[jj] = 0.f; }

    for (int it = 0; it < nIt; it++) {
        const int cur = it & 1;
        __syncthreads();   // pair-it sets staged; Rbuf free (epilogue done)

        float ra[5], rb[5];
        const int pn = lo + 2 * it + 2;          // next pair (clamped loads ok)
        ldpair(pn, ra, rb);
        gemm(cur * 2 + 0, Rbuf0);
        stpair((cur ^ 1) * 2 + 0, ra, rb);
        ldpair(pn + 1, ra, rb);
        gemm(cur * 2 + 1, Rbuf1);
        stpair((cur ^ 1) * 2 + 1, ra, rb);

        __syncthreads();   // Rbuf0/1 ready

        // ---- epilogue: two finished rows per iteration ----
        const int ss0 = 2 * it;
        const bool fin0 = ss0 >= 2;
        const bool fin1 = (ss0 + 1 >= 2) && (ss0 + 1 < steps);
        const int iy = lo + ss0 - 2;
        unsigned long long c0 = ~0ull, c1 = ~0ull;
        const unsigned jr0 = (unsigned)((iy + d) * W + ejx0);
        const unsigned jr1 = jr0 + W;
#pragma unroll
        for (int jj = 0; jj < 16; jj++) {
            float g0 = R00[jj] + R01[jj] + R02[jj];
            float g1 = R10[jj] + R11[jj] + R12[jj];
            float s01 = g0 + g1;
            if (fin0) {
                float d2 = A2[jj] + g0;
                unsigned long long key =
                    ((unsigned long long)__float_as_uint(d2) << 12) | (jr0 + jj);
                c0 = key < c0 ? key : c0;
            }
            if (fin1) {
                float d2 = A1[jj] + s01;
                unsigned long long key =
                    ((unsigned long long)__float_as_uint(d2) << 12) | (jr1 + jj);
                c1 = key < c1 ? key : c1;
            }
            A2[jj] = s01;
            A1[jj] = g1;
        }
        if (fin0) atomicMin(gb + iy * W, c0);
        if (fin1) atomicMin(gb + (iy + 1) * W, c1);
    }
}

// ---------------------------------------------------------------------------
// Decode packed keys -> (jy, jx, d2).
// ---------------------------------------------------------------------------
__global__ void reduce_kernel(float* __restrict__ out) {
    int idx = blockIdx.x * blockDim.x + threadIdx.x;
    if (idx >= NB * HW) return;
    int b = idx >> 12, q = idx & (HW - 1);
    unsigned long long best = g_best[idx];
    int j = (int)(best & 4095u);
    float d2 = __uint_as_float((unsigned)(best >> 12));
    out[(size_t)b * 2 * HW + q]                    = (float)(j >> 6);
    out[(size_t)b * 2 * HW + HW + q]               = (float)(j & 63);
    out[(size_t)NB * 2 * HW + (size_t)b * HW + q]  = d2;
}

extern "C" void kernel_launch(void* const* d_in, const int* in_sizes, int n_in,
                              void* d_out, int out_size) {
    const float* s = (const float*)d_in[0];
    const float* t = (const float*)d_in[1];
    float* out = (float*)d_out;

    cudaFuncSetAttribute(nn_kernel, cudaFuncAttributeMaxDynamicSharedMemorySize,
                         SMEM_BYTES);

    norm1_kernel<<<dim3((NB * HW + 255) / 256, 2), 256>>>(s, t);
    nn_kernel<<<NDIAG * NB, 256, SMEM_BYTES>>>(t);
    reduce_kernel<<<(NB * HW + 255) / 256, 256>>>(out);
}